// round 15
// baseline (speedup 1.0000x reference)
#include <cuda_runtime.h>
#include <cuda_fp16.h>
#include <cstdint>

// Conv2DUF via legacy mma.sync FP16 implicit GEMM (compute_103-safe).
// CTA 128x256 (all couts), 512 threads = 16 compute warps (32x64 tiles, 4m x 4n),
// BK=64, 3-stage SELF-PRODUCED mbarrier ring (no bar.sync in k-loop), 1 CTA/SM.
// K reordered k'=(kh*3+kw)*128+c. full[s] via cp.async.mbarrier.arrive.noinc (cnt 512),
// empty[s] via mbarrier.arrive (cnt 512) gating stage reuse.

namespace {
constexpr int HW = 3136;        // 56*56
constexpr int KT = 18;          // 1152/64
constexpr int STG = 49152;      // stage: A 16KB @ +0, B 32KB @ +16384
constexpr int RING = 3;
constexpr int MBOFF = RING * STG;            // 147456; mbarriers after ring
constexpr int SMEM_DYN = MBOFF + 128;
constexpr int NXBLK = 12544;
constexpr int EPAD = 132;       // epilogue pitch (floats); sc = 256*132*4 = 135168 B
}

__device__ __half g_xh[32 * HW * 128];   // NHWC fp16
__device__ __half g_wh[256 * 1152];      // [cout][k'] fp16

struct alignas(8) Half4 { __half2 a, b; };

__device__ __forceinline__ uint32_t s2u(const void* p) {
    uint32_t a;
    asm("{.reg .u64 t; cvta.to.shared.u64 t, %1; cvt.u32.u64 %0, t;}" : "=r"(a) : "l"(p));
    return a;
}
__device__ __forceinline__ uint32_t swz(uint32_t o) { return o ^ ((o >> 3) & 0x70); }
__device__ __forceinline__ void cp16(uint32_t dst, const void* src, int sz) {
    asm volatile("cp.async.cg.shared.global [%0], [%1], 16, %2;" :: "r"(dst), "l"(src), "r"(sz));
}
__device__ __forceinline__ void cpam_noinc(uint32_t mb) {
    asm volatile("cp.async.mbarrier.arrive.noinc.shared::cta.b64 [%0];" :: "r"(mb) : "memory");
}
__device__ __forceinline__ void mbar_init(uint32_t mb, uint32_t cnt) {
    asm volatile("mbarrier.init.shared.b64 [%0], %1;" :: "r"(mb), "r"(cnt) : "memory");
}
__device__ __forceinline__ void mbar_arrive(uint32_t mb) {
    asm volatile("mbarrier.arrive.shared.b64 _, [%0];" :: "r"(mb) : "memory");
}
__device__ __forceinline__ void mbar_wait(uint32_t mb, uint32_t parity) {
    asm volatile("{\n\t.reg .pred P;\n\tWL_%=:\n\t"
                 "mbarrier.try_wait.parity.acquire.cta.shared::cta.b64 P, [%0], %1, 0x989680;\n\t"
                 "@P bra.uni WD_%=;\n\tbra.uni WL_%=;\n\tWD_%=:\n\t}"
                 :: "r"(mb), "r"(parity) : "memory");
}
__device__ __forceinline__ void ldsm4(uint32_t* r, uint32_t addr) {
    asm volatile("ldmatrix.sync.aligned.m8n8.x4.shared.b16 {%0,%1,%2,%3}, [%4];"
                 : "=r"(r[0]), "=r"(r[1]), "=r"(r[2]), "=r"(r[3]) : "r"(addr));
}
__device__ __forceinline__ void mma16(float* c, const uint32_t* a, uint32_t b0, uint32_t b1) {
    asm volatile("mma.sync.aligned.m16n8k16.row.col.f32.f16.f16.f32 "
                 "{%0,%1,%2,%3},{%4,%5,%6,%7},{%8,%9},{%0,%1,%2,%3};"
                 : "+f"(c[0]), "+f"(c[1]), "+f"(c[2]), "+f"(c[3])
                 : "r"(a[0]), "r"(a[1]), "r"(a[2]), "r"(a[3]), "r"(b0), "r"(b1));
}

// ---- prepass: x NCHW -> NHWC fp16 (8B stores), and w[k][n] -> [n][k'] fp16 ----
__global__ void prepass_kernel(const float* __restrict__ x, const float* __restrict__ w) {
    __shared__ float t[32][33];
    const int tid = threadIdx.x;
    const int tx = tid & 31, ty = tid >> 5;
    const int bx = blockIdx.x;
    if (bx < NXBLK) {
        const int n  = bx / 392;
        const int r  = bx - n * 392;
        const int p0 = (r % 98) * 32;
        const int c0 = (r / 98) * 32;
        const float* xp = x + ((size_t)n * 128 + c0) * HW + p0;
#pragma unroll
        for (int i = ty; i < 32; i += 8)
            t[i][tx] = xp[(size_t)i * HW + tx];
        __syncthreads();
        const int prow = tid >> 3, cq = tid & 7;
        __half h0 = __float2half_rn(t[cq * 4 + 0][prow]);
        __half h1 = __float2half_rn(t[cq * 4 + 1][prow]);
        __half h2 = __float2half_rn(t[cq * 4 + 2][prow]);
        __half h3 = __float2half_rn(t[cq * 4 + 3][prow]);
        Half4 v{__halves2half2(h0, h1), __halves2half2(h2, h3)};
        __half* xo = g_xh + ((size_t)n * HW + p0 + prow) * 128 + c0 + cq * 4;
        *reinterpret_cast<Half4*>(xo) = v;
    } else {
        const int idx = bx - NXBLK;
        const int kp0 = (idx % 36) * 32;
        const int n0  = (idx / 36) * 32;
        for (int i = ty; i < 32; i += 8) {
            int kp = kp0 + i;
            int rr = kp >> 7, c = kp & 127;
            t[i][tx] = w[(c * 9 + rr) * 256 + n0 + tx];
        }
        __syncthreads();
        for (int i = ty; i < 32; i += 8)
            g_wh[(size_t)(n0 + i) * 1152 + kp0 + tx] = __float2half_rn(t[tx][i]);
    }
}

// ---- main kernel: CTA 128x256, 512 threads, self-produced mbarrier ring ----
__global__ __launch_bounds__(512, 1)
void conv_mma_kernel(const float* __restrict__ bias, float* __restrict__ out) {
    extern __shared__ char smem[];
    const uint32_t sb = s2u(smem);
    const uint32_t mbF = sb + MBOFF;        // full[3]  @ +0,8,16
    const uint32_t mbE = mbF + 24;          // empty[3] @ +24,32,40
    const int tid = threadIdx.x, wid = tid >> 5, lid = tid & 31;
    const int bx = blockIdx.x;              // 784 M-tiles

    if (tid == 0) {
#pragma unroll
        for (int s = 0; s < RING; s++) {
            mbar_init(mbF + s * 8, 512);    // all threads cpam.noinc
            mbar_init(mbE + s * 8, 512);    // all threads arrive
        }
    }
    __syncthreads();

    // ---- producer mapping (all 512 threads) ----
    // A: row = tid>>2 (0..127), chunks j = (tid&3)*2, +1   (2 cp16)
    // B: row = tid>>1 (0..255), chunks j = (tid&1)*4..+3    (4 cp16)
    const int arow = tid >> 2, aj0 = (tid & 3) * 2;
    const int brow = tid >> 1, bj0 = (tid & 1) * 4;
    const int p = bx * 128 + arow;
    const int nimg = p / HW;
    const int rem = p - nimg * HW;
    const int yp = rem / 56, xp = rem - yp * 56;
    const __half* xrow = g_xh + ((size_t)nimg * HW + (yp - 1) * 56 + (xp - 1)) * 128;
    const __half* wrow = g_wh + (size_t)brow * 1152;

    uint32_t dstA[2], dstB[4];
#pragma unroll
    for (int j = 0; j < 2; j++) dstA[j] = swz(arow * 128 + (aj0 + j) * 16);
#pragma unroll
    for (int j = 0; j < 4; j++) dstB[j] = swz(brow * 128 + (bj0 + j) * 16);

    auto issue = [&](int kt) {
        const int s = kt % RING;
        const int r = kt >> 1;
        const int kh = r / 3, kw = r - kh * 3;
        const int cb = (kt & 1) * 64;
        const bool ok = ((unsigned)(yp + kh - 1) < 56u) && ((unsigned)(xp + kw - 1) < 56u);
        const __half* asrc = ok ? (xrow + (kh * 56 + kw) * 128 + cb) : g_xh;
        const int sz = ok ? 16 : 0;
        const uint32_t ad = sb + s * STG;
        const uint32_t bd = ad + 16384;
        const __half* bsrc = wrow + kt * 64;
#pragma unroll
        for (int j = 0; j < 2; j++)
            cp16(ad + dstA[j], asrc + (ok ? (aj0 + j) * 8 : 0), sz);
#pragma unroll
        for (int j = 0; j < 4; j++)
            cp16(bd + dstB[j], bsrc + (bj0 + j) * 8, 16);
        cpam_noinc(mbF + s * 8);             // deferred arrive when copies land
    };

    issue(0); issue(1); issue(2);

    float acc[2][8][4];
#pragma unroll
    for (int i = 0; i < 2; i++)
#pragma unroll
        for (int j = 0; j < 8; j++)
#pragma unroll
            for (int q = 0; q < 4; q++) acc[i][j][q] = 0.f;

    const int m0  = (wid & 3) * 32;          // 4 m-warps
    const int n0w = (wid >> 2) * 64;         // 4 n-warps
    const int rowL = lid & 15;
    const int colL = (lid >> 4) * 16;

    for (int kt = 0; kt < KT; kt++) {
        const int s = kt % RING;
        const uint32_t par = (uint32_t)((kt / RING) & 1);
        mbar_wait(mbF + s * 8, par);
        const uint32_t aT = sb + s * STG;
        const uint32_t bT = aT + 16384;
#pragma unroll
        for (int ss = 0; ss < 4; ss++) {
            uint32_t a[2][4], b[4][4];
#pragma unroll
            for (int mi = 0; mi < 2; mi++)
                ldsm4(a[mi], aT + swz((m0 + mi * 16 + rowL) * 128 + ss * 32 + colL));
#pragma unroll
            for (int nj = 0; nj < 4; nj++)
                ldsm4(b[nj], bT + swz((n0w + nj * 16 + rowL) * 128 + ss * 32 + colL));
#pragma unroll
            for (int mi = 0; mi < 2; mi++)
#pragma unroll
                for (int ni = 0; ni < 8; ni++)
                    mma16(acc[mi][ni], a[mi], b[ni >> 1][ni & 1], b[ni >> 1][(ni & 1) + 2]);
        }
        mbar_arrive(mbE + s * 8);            // done reading stage s this round
        if (kt + RING < KT) {
            mbar_wait(mbE + s * 8, par);     // all 512 threads done with round kt
            issue(kt + RING);                // refill slot s
        }
    }

    // ---- epilogue: acc -> smem [channel][pixel] -> coalesced float4 NCHW stores ----
    __syncthreads();                         // uniform; ring no longer needed
    float* sc = reinterpret_cast<float*>(smem);   // [256][EPAD] floats
#pragma unroll
    for (int mi = 0; mi < 2; mi++) {
        const int mr = m0 + mi * 16 + (lid >> 2);
#pragma unroll
        for (int ni = 0; ni < 8; ni++) {
            const int c0 = n0w + ni * 8 + (lid & 3) * 2;
            sc[c0 * EPAD + mr]           = acc[mi][ni][0];
            sc[(c0 + 1) * EPAD + mr]     = acc[mi][ni][1];
            sc[c0 * EPAD + mr + 8]       = acc[mi][ni][2];
            sc[(c0 + 1) * EPAD + mr + 8] = acc[mi][ni][3];
        }
    }
    __syncthreads();

    const int base = bx * 128;
    const int img0 = base / HW;
    const int off0 = base - img0 * HW;
#pragma unroll
    for (int j = 0; j < 16; j++) {
        const int c = wid * 16 + j;          // 16 warps x 16 channels = 256
        float4 v = *reinterpret_cast<const float4*>(&sc[c * EPAD + lid * 4]);
        const float bb = bias[c];
        v.x += bb; v.y += bb; v.z += bb; v.w += bb;
        int pix = off0 + lid * 4;
        int img = img0;
        if (pix >= HW) { pix -= HW; img++; }
        *reinterpret_cast<float4*>(out + ((size_t)(img * 256 + c)) * HW + pix) = v;
    }
}

extern "C" void kernel_launch(void* const* d_in, const int* in_sizes, int n_in,
                              void* d_out, int out_size) {
    const float* x    = (const float*)d_in[0];
    const float* w    = (const float*)d_in[1];
    const float* bias = (const float*)d_in[2];
    float* out        = (float*)d_out;

    cudaFuncSetAttribute(conv_mma_kernel, cudaFuncAttributeMaxDynamicSharedMemorySize, SMEM_DYN);

    prepass_kernel<<<NXBLK + 288, 256>>>(x, w);
    conv_mma_kernel<<<784, 512, SMEM_DYN>>>(bias, out);
}

// round 16
// speedup vs baseline: 1.0517x; 1.0517x over previous
#include <cuda_runtime.h>
#include <cuda_fp16.h>
#include <cstdint>

// Conv2DUF via legacy mma.sync FP16 implicit GEMM (compute_103-safe).
// 4 sync domains per SM: CTA 64x128, 128 threads (4 warps x 32x64 tiles),
// BK=64, 2-buffer cp.async ring (48KB/CTA), 4 CTAs/SM, grid 1568x2.
// K reordered k'=(kh*3+kw)*128+c. Prepass: x->NHWC fp16, w->[n][k'] fp16.

namespace {
constexpr int HW = 3136;        // 56*56
constexpr int KT = 18;          // 1152/64
constexpr int STG = 24576;      // stage: A 8KB @ +0, B 16KB @ +8192
constexpr int SMEM_DYN = 2 * STG;    // 48 KB
constexpr int NXBLK = 12544;
constexpr int EPAD = 68;        // epilogue scratch pitch (floats); 128*68*4 = 34.8KB
}

__device__ __half g_xh[32 * HW * 128];   // NHWC fp16
__device__ __half g_wh[256 * 1152];      // [cout][k'] fp16

struct alignas(8) Half4 { __half2 a, b; };

__device__ __forceinline__ uint32_t s2u(const void* p) {
    uint32_t a;
    asm("{.reg .u64 t; cvta.to.shared.u64 t, %1; cvt.u32.u64 %0, t;}" : "=r"(a) : "l"(p));
    return a;
}
__device__ __forceinline__ uint32_t swz(uint32_t o) { return o ^ ((o >> 3) & 0x70); }
__device__ __forceinline__ void cp16(uint32_t dst, const void* src, int sz) {
    asm volatile("cp.async.cg.shared.global [%0], [%1], 16, %2;" :: "r"(dst), "l"(src), "r"(sz));
}
__device__ __forceinline__ void ldsm4(uint32_t* r, uint32_t addr) {
    asm volatile("ldmatrix.sync.aligned.m8n8.x4.shared.b16 {%0,%1,%2,%3}, [%4];"
                 : "=r"(r[0]), "=r"(r[1]), "=r"(r[2]), "=r"(r[3]) : "r"(addr));
}
__device__ __forceinline__ void mma16(float* c, const uint32_t* a, uint32_t b0, uint32_t b1) {
    asm volatile("mma.sync.aligned.m16n8k16.row.col.f32.f16.f16.f32 "
                 "{%0,%1,%2,%3},{%4,%5,%6,%7},{%8,%9},{%0,%1,%2,%3};"
                 : "+f"(c[0]), "+f"(c[1]), "+f"(c[2]), "+f"(c[3])
                 : "r"(a[0]), "r"(a[1]), "r"(a[2]), "r"(a[3]), "r"(b0), "r"(b1));
}

// ---- prepass: x NCHW -> NHWC fp16 (8B stores), and w[k][n] -> [n][k'] fp16 ----
__global__ void prepass_kernel(const float* __restrict__ x, const float* __restrict__ w) {
    __shared__ float t[32][33];
    const int tid = threadIdx.x;
    const int tx = tid & 31, ty = tid >> 5;
    const int bx = blockIdx.x;
    if (bx < NXBLK) {
        const int n  = bx / 392;
        const int r  = bx - n * 392;
        const int p0 = (r % 98) * 32;
        const int c0 = (r / 98) * 32;
        const float* xp = x + ((size_t)n * 128 + c0) * HW + p0;
#pragma unroll
        for (int i = ty; i < 32; i += 8)
            t[i][tx] = xp[(size_t)i * HW + tx];
        __syncthreads();
        const int prow = tid >> 3, cq = tid & 7;
        __half h0 = __float2half_rn(t[cq * 4 + 0][prow]);
        __half h1 = __float2half_rn(t[cq * 4 + 1][prow]);
        __half h2 = __float2half_rn(t[cq * 4 + 2][prow]);
        __half h3 = __float2half_rn(t[cq * 4 + 3][prow]);
        Half4 v{__halves2half2(h0, h1), __halves2half2(h2, h3)};
        __half* xo = g_xh + ((size_t)n * HW + p0 + prow) * 128 + c0 + cq * 4;
        *reinterpret_cast<Half4*>(xo) = v;
    } else {
        const int idx = bx - NXBLK;
        const int kp0 = (idx % 36) * 32;
        const int n0  = (idx / 36) * 32;
        for (int i = ty; i < 32; i += 8) {
            int kp = kp0 + i;
            int rr = kp >> 7, c = kp & 127;
            t[i][tx] = w[(c * 9 + rr) * 256 + n0 + tx];
        }
        __syncthreads();
        for (int i = ty; i < 32; i += 8)
            g_wh[(size_t)(n0 + i) * 1152 + kp0 + tx] = __float2half_rn(t[tx][i]);
    }
}

// ---- main kernel: CTA 64x128, 4 warps, 4 CTAs/SM ----
__global__ __launch_bounds__(128, 4)
void conv_mma_kernel(const float* __restrict__ bias, float* __restrict__ out) {
    extern __shared__ char smem[];
    const uint32_t sb = s2u(smem);
    const int tid = threadIdx.x, wid = tid >> 5, lid = tid & 31;
    const int bx = blockIdx.x;              // 1568 M-tiles (64 pixels each)
    const int bn0 = blockIdx.y * 128;       // N tile

    // A producer: row = tid>>1 (0..63), qh picks 4 of 8 chunks
    const int arow = tid >> 1, qh = tid & 1;
    const int p = bx * 64 + arow;
    const int nimg = p / HW;
    const int rem = p - nimg * HW;
    const int yp = rem / 56, xp = rem - yp * 56;
    const __half* xrow = g_xh + ((size_t)nimg * HW + (yp - 1) * 56 + (xp - 1)) * 128;
    // B producer: each thread owns cout row = tid (8 chunks)
    const __half* wrow = g_wh + (size_t)(bn0 + tid) * 1152;

    uint32_t dstA[4], dstB[8];
#pragma unroll
    for (int j = 0; j < 4; j++)
        dstA[j] = swz(arow * 128 + (qh * 4 + j) * 16);
#pragma unroll
    for (int j = 0; j < 8; j++)
        dstB[j] = swz(tid * 128 + j * 16);

    auto issue = [&](int kt, int buf) {
        const int r = kt >> 1;
        const int kh = r / 3, kw = r - kh * 3;
        const int cb = (kt & 1) * 64;
        const bool ok = ((unsigned)(yp + kh - 1) < 56u) && ((unsigned)(xp + kw - 1) < 56u);
        const __half* asrc = ok ? (xrow + (kh * 56 + kw) * 128 + cb) : g_xh;
        const int sz = ok ? 16 : 0;
        const uint32_t ad = sb + buf * STG;
        const uint32_t bd = ad + 8192;
        const __half* bsrc = wrow + kt * 64;
#pragma unroll
        for (int j = 0; j < 4; j++)
            cp16(ad + dstA[j], asrc + (ok ? (qh * 4 + j) * 8 : 0), sz);
#pragma unroll
        for (int j = 0; j < 8; j++)
            cp16(bd + dstB[j], bsrc + j * 8, 16);
        asm volatile("cp.async.commit_group;" ::: "memory");
    };

    issue(0, 0);
    issue(1, 1);

    float acc[2][8][4];
#pragma unroll
    for (int i = 0; i < 2; i++)
#pragma unroll
        for (int j = 0; j < 8; j++)
#pragma unroll
            for (int q = 0; q < 4; q++) acc[i][j][q] = 0.f;

    const int m0  = (wid & 1) * 32;          // 2 m-warps
    const int n0w = (wid >> 1) * 64;         // 2 n-warps
    const int rowL = lid & 15;
    const int colL = (lid >> 4) * 16;

    for (int kt = 0; kt < KT; kt++) {
        if (kt < KT - 1) asm volatile("cp.async.wait_group 1;" ::: "memory");
        else             asm volatile("cp.async.wait_group 0;" ::: "memory");
        __syncthreads();
        const int buf = kt & 1;
        const uint32_t aT = sb + buf * STG;
        const uint32_t bT = aT + 8192;
#pragma unroll
        for (int s = 0; s < 4; s++) {
            uint32_t a[2][4], b[4][4];
#pragma unroll
            for (int mi = 0; mi < 2; mi++)
                ldsm4(a[mi], aT + swz((m0 + mi * 16 + rowL) * 128 + s * 32 + colL));
#pragma unroll
            for (int nj = 0; nj < 4; nj++)
                ldsm4(b[nj], bT + swz((n0w + nj * 16 + rowL) * 128 + s * 32 + colL));
#pragma unroll
            for (int mi = 0; mi < 2; mi++)
#pragma unroll
                for (int ni = 0; ni < 8; ni++)
                    mma16(acc[mi][ni], a[mi], b[ni >> 1][ni & 1], b[ni >> 1][(ni & 1) + 2]);
        }
        __syncthreads();
        if (kt + 2 < KT) issue(kt + 2, buf);
    }

    // ---- epilogue: acc -> smem [channel][pixel] -> coalesced float4 NCHW stores ----
    __syncthreads();
    float* sc = reinterpret_cast<float*>(smem);   // [128][EPAD] floats (34.8KB)
#pragma unroll
    for (int mi = 0; mi < 2; mi++) {
        const int mr = m0 + mi * 16 + (lid >> 2);
#pragma unroll
        for (int ni = 0; ni < 8; ni++) {
            const int c0 = n0w + ni * 8 + (lid & 3) * 2;
            sc[c0 * EPAD + mr]           = acc[mi][ni][0];
            sc[(c0 + 1) * EPAD + mr]     = acc[mi][ni][1];
            sc[c0 * EPAD + mr + 8]       = acc[mi][ni][2];
            sc[(c0 + 1) * EPAD + mr + 8] = acc[mi][ni][3];
        }
    }
    __syncthreads();

    const int img0 = bx / 49;
    const int off0 = (bx - img0 * 49) * 64;       // 64-aligned: never crosses an image
#pragma unroll
    for (int j = 0; j < 16; j++) {
        const int c = wid * 32 + j * 2 + (lid >> 4);      // 2 channels per iter, full warp
        float4 v = *reinterpret_cast<const float4*>(&sc[c * EPAD + (lid & 15) * 4]);
        const float bb = bias[bn0 + c];
        v.x += bb; v.y += bb; v.z += bb; v.w += bb;
        *reinterpret_cast<float4*>(
            out + ((size_t)(img0 * 256 + bn0 + c)) * HW + off0 + (lid & 15) * 4) = v;
    }
}

extern "C" void kernel_launch(void* const* d_in, const int* in_sizes, int n_in,
                              void* d_out, int out_size) {
    const float* x    = (const float*)d_in[0];
    const float* w    = (const float*)d_in[1];
    const float* bias = (const float*)d_in[2];
    float* out        = (float*)d_out;

    cudaFuncSetAttribute(conv_mma_kernel, cudaFuncAttributeMaxDynamicSharedMemorySize, SMEM_DYN);

    prepass_kernel<<<NXBLK + 288, 256>>>(x, w);
    conv_mma_kernel<<<dim3(1568, 2), 128, SMEM_DYN>>>(bias, out);
}

// round 17
// speedup vs baseline: 1.4523x; 1.3810x over previous
#include <cuda_runtime.h>
#include <cuda_fp16.h>
#include <cstdint>

// Conv2DUF via legacy mma.sync FP16 implicit GEMM (compute_103-safe).
// 24 warps/SM: CTA 64x128, 256 threads (8 warps x 32x32 tiles, 2m x 4n),
// BK=64, 3-stage cp.async ring (24KB/stage, 72KB/CTA), 3 CTAs/SM.
// K reordered k'=(kh*3+kw)*128+c. Prepass: x->NHWC fp16, w->[n][k'] fp16.

namespace {
constexpr int HW = 3136;        // 56*56
constexpr int KT = 18;          // 1152/64
constexpr int STG = 24576;      // stage: A 8KB @ +0, B 16KB @ +8192
constexpr int RING = 3;
constexpr int SMEM_DYN = RING * STG;  // 73728 B
constexpr int NXBLK = 12544;
constexpr int EPAD = 68;        // epilogue scratch pitch (floats); 128*68*4 = 34.8KB
}

__device__ __half g_xh[32 * HW * 128];   // NHWC fp16
__device__ __half g_wh[256 * 1152];      // [cout][k'] fp16

struct alignas(8) Half4 { __half2 a, b; };

__device__ __forceinline__ uint32_t s2u(const void* p) {
    uint32_t a;
    asm("{.reg .u64 t; cvta.to.shared.u64 t, %1; cvt.u32.u64 %0, t;}" : "=r"(a) : "l"(p));
    return a;
}
__device__ __forceinline__ uint32_t swz(uint32_t o) { return o ^ ((o >> 3) & 0x70); }
__device__ __forceinline__ void cp16(uint32_t dst, const void* src, int sz) {
    asm volatile("cp.async.cg.shared.global [%0], [%1], 16, %2;" :: "r"(dst), "l"(src), "r"(sz));
}
__device__ __forceinline__ void ldsm4(uint32_t* r, uint32_t addr) {
    asm volatile("ldmatrix.sync.aligned.m8n8.x4.shared.b16 {%0,%1,%2,%3}, [%4];"
                 : "=r"(r[0]), "=r"(r[1]), "=r"(r[2]), "=r"(r[3]) : "r"(addr));
}
__device__ __forceinline__ void mma16(float* c, const uint32_t* a, uint32_t b0, uint32_t b1) {
    asm volatile("mma.sync.aligned.m16n8k16.row.col.f32.f16.f16.f32 "
                 "{%0,%1,%2,%3},{%4,%5,%6,%7},{%8,%9},{%0,%1,%2,%3};"
                 : "+f"(c[0]), "+f"(c[1]), "+f"(c[2]), "+f"(c[3])
                 : "r"(a[0]), "r"(a[1]), "r"(a[2]), "r"(a[3]), "r"(b0), "r"(b1));
}

// ---- prepass: x NCHW -> NHWC fp16 (8B stores), and w[k][n] -> [n][k'] fp16 ----
__global__ void prepass_kernel(const float* __restrict__ x, const float* __restrict__ w) {
    __shared__ float t[32][33];
    const int tid = threadIdx.x;
    const int tx = tid & 31, ty = tid >> 5;
    const int bx = blockIdx.x;
    if (bx < NXBLK) {
        const int n  = bx / 392;
        const int r  = bx - n * 392;
        const int p0 = (r % 98) * 32;
        const int c0 = (r / 98) * 32;
        const float* xp = x + ((size_t)n * 128 + c0) * HW + p0;
#pragma unroll
        for (int i = ty; i < 32; i += 8)
            t[i][tx] = xp[(size_t)i * HW + tx];
        __syncthreads();
        const int prow = tid >> 3, cq = tid & 7;
        __half h0 = __float2half_rn(t[cq * 4 + 0][prow]);
        __half h1 = __float2half_rn(t[cq * 4 + 1][prow]);
        __half h2 = __float2half_rn(t[cq * 4 + 2][prow]);
        __half h3 = __float2half_rn(t[cq * 4 + 3][prow]);
        Half4 v{__halves2half2(h0, h1), __halves2half2(h2, h3)};
        __half* xo = g_xh + ((size_t)n * HW + p0 + prow) * 128 + c0 + cq * 4;
        *reinterpret_cast<Half4*>(xo) = v;
    } else {
        const int idx = bx - NXBLK;
        const int kp0 = (idx % 36) * 32;
        const int n0  = (idx / 36) * 32;
        for (int i = ty; i < 32; i += 8) {
            int kp = kp0 + i;
            int rr = kp >> 7, c = kp & 127;
            t[i][tx] = w[(c * 9 + rr) * 256 + n0 + tx];
        }
        __syncthreads();
        for (int i = ty; i < 32; i += 8)
            g_wh[(size_t)(n0 + i) * 1152 + kp0 + tx] = __float2half_rn(t[tx][i]);
    }
}

// ---- main kernel: CTA 64x128, 8 warps (32x32 tiles), 3 CTAs/SM ----
__global__ __launch_bounds__(256, 3)
void conv_mma_kernel(const float* __restrict__ bias, float* __restrict__ out) {
    extern __shared__ char smem[];
    const uint32_t sb = s2u(smem);
    const int tid = threadIdx.x, wid = tid >> 5, lid = tid & 31;
    const int bx = blockIdx.x;              // 1568 M-tiles (64 pixels)
    const int bn0 = blockIdx.y * 128;       // N tile

    // A producer: row = tid>>2 (0..63), 2 of 8 chunks
    const int arow = tid >> 2, aj0 = (tid & 3) * 2;
    // B producer: row = tid>>1 (0..127), 4 of 8 chunks
    const int brow = tid >> 1, bj0 = (tid & 1) * 4;

    const int p = bx * 64 + arow;
    const int nimg = p / HW;
    const int rem = p - nimg * HW;
    const int yp = rem / 56, xp = rem - yp * 56;
    const __half* xrow = g_xh + ((size_t)nimg * HW + (yp - 1) * 56 + (xp - 1)) * 128;
    const __half* wrow = g_wh + (size_t)(bn0 + brow) * 1152;

    uint32_t dstA[2], dstB[4];
#pragma unroll
    for (int j = 0; j < 2; j++) dstA[j] = swz(arow * 128 + (aj0 + j) * 16);
#pragma unroll
    for (int j = 0; j < 4; j++) dstB[j] = swz(brow * 128 + (bj0 + j) * 16);

    auto issue = [&](int kt, int buf) {
        const int r = kt >> 1;
        const int kh = r / 3, kw = r - kh * 3;
        const int cb = (kt & 1) * 64;
        const bool ok = ((unsigned)(yp + kh - 1) < 56u) && ((unsigned)(xp + kw - 1) < 56u);
        const __half* asrc = ok ? (xrow + (kh * 56 + kw) * 128 + cb) : g_xh;
        const int sz = ok ? 16 : 0;
        const uint32_t ad = sb + buf * STG;
        const uint32_t bd = ad + 8192;
        const __half* bsrc = wrow + kt * 64;
#pragma unroll
        for (int j = 0; j < 2; j++)
            cp16(ad + dstA[j], asrc + (ok ? (aj0 + j) * 8 : 0), sz);
#pragma unroll
        for (int j = 0; j < 4; j++)
            cp16(bd + dstB[j], bsrc + (bj0 + j) * 8, 16);
        asm volatile("cp.async.commit_group;" ::: "memory");
    };

    issue(0, 0);
    issue(1, 1);

    float acc[2][4][4];
#pragma unroll
    for (int i = 0; i < 2; i++)
#pragma unroll
        for (int j = 0; j < 4; j++)
#pragma unroll
            for (int q = 0; q < 4; q++) acc[i][j][q] = 0.f;

    const int m0  = (wid & 1) * 32;          // 2 m-warps
    const int n0w = (wid >> 1) * 32;         // 4 n-warps
    const int rowL = lid & 15;
    const int colL = (lid >> 4) * 16;

    int buf = 0, pbuf = 2;
    for (int kt = 0; kt < KT; kt++) {
        if (kt < KT - 1) asm volatile("cp.async.wait_group 1;" ::: "memory");
        else             asm volatile("cp.async.wait_group 0;" ::: "memory");
        __syncthreads();
        if (kt + 2 < KT) issue(kt + 2, pbuf);

        const uint32_t aT = sb + buf * STG;
        const uint32_t bT = aT + 8192;
#pragma unroll
        for (int s = 0; s < 4; s++) {
            uint32_t a[2][4], b[2][4];
#pragma unroll
            for (int mi = 0; mi < 2; mi++)
                ldsm4(a[mi], aT + swz((m0 + mi * 16 + rowL) * 128 + s * 32 + colL));
#pragma unroll
            for (int nj = 0; nj < 2; nj++)
                ldsm4(b[nj], bT + swz((n0w + nj * 16 + rowL) * 128 + s * 32 + colL));
#pragma unroll
            for (int mi = 0; mi < 2; mi++)
#pragma unroll
                for (int ni = 0; ni < 4; ni++)
                    mma16(acc[mi][ni], a[mi], b[ni >> 1][ni & 1], b[ni >> 1][(ni & 1) + 2]);
        }
        buf  = (buf == 2)  ? 0 : buf + 1;
        pbuf = (pbuf == 2) ? 0 : pbuf + 1;
    }

    // ---- epilogue: acc -> smem [channel][pixel] -> coalesced float4 NCHW stores ----
    __syncthreads();
    float* sc = reinterpret_cast<float*>(smem);   // [128][EPAD] floats (34.8KB)
#pragma unroll
    for (int mi = 0; mi < 2; mi++) {
        const int mr = m0 + mi * 16 + (lid >> 2);
#pragma unroll
        for (int ni = 0; ni < 4; ni++) {
            const int c0 = n0w + ni * 8 + (lid & 3) * 2;
            sc[c0 * EPAD + mr]           = acc[mi][ni][0];
            sc[(c0 + 1) * EPAD + mr]     = acc[mi][ni][1];
            sc[c0 * EPAD + mr + 8]       = acc[mi][ni][2];
            sc[(c0 + 1) * EPAD + mr + 8] = acc[mi][ni][3];
        }
    }
    __syncthreads();

    const int img0 = bx / 49;
    const int off0 = (bx - img0 * 49) * 64;       // 64-aligned: never crosses an image
#pragma unroll
    for (int j = 0; j < 8; j++) {
        const int c = wid * 16 + j * 2 + (lid >> 4);      // 2 channels x 16 px-quads
        float4 v = *reinterpret_cast<const float4*>(&sc[c * EPAD + (lid & 15) * 4]);
        const float bb = bias[bn0 + c];
        v.x += bb; v.y += bb; v.z += bb; v.w += bb;
        *reinterpret_cast<float4*>(
            out + ((size_t)(img0 * 256 + bn0 + c)) * HW + off0 + (lid & 15) * 4) = v;
    }
}

extern "C" void kernel_launch(void* const* d_in, const int* in_sizes, int n_in,
                              void* d_out, int out_size) {
    const float* x    = (const float*)d_in[0];
    const float* w    = (const float*)d_in[1];
    const float* bias = (const float*)d_in[2];
    float* out        = (float*)d_out;

    cudaFuncSetAttribute(conv_mma_kernel, cudaFuncAttributeMaxDynamicSharedMemorySize, SMEM_DYN);

    prepass_kernel<<<NXBLK + 288, 256>>>(x, w);
    conv_mma_kernel<<<dim3(1568, 2), 256, SMEM_DYN>>>(bias, out);
}